// round 7
// baseline (speedup 1.0000x reference)
#include <cuda_runtime.h>

// Problem constants
constexpr int B = 512, T = 365, C = 10, P = 64;
constexpr int K  = T * C;       // 3650
constexpr int KE = K + T;       // 4015
constexpr int KC  = 64;         // k per chunk
constexpr int NKC = 63;         // chunks cover [0, 4032) ⊇ KE

// Output layout: [output_seq BK][input_seq BK][distances BP][indices B][label B][mask BT]
constexpr int O1 = B * K;
constexpr int O2 = O1 + B * K;
constexpr int O3 = O2 + B * P;
constexpr int O4 = O3 + B;
constexpr int O5 = O4 + B;

__device__ float g_part[NKC * B * P];   // split-K partials (~8.3 MB, L2)

// smem sizes (floats)
constexpr int SMA = 64 * 128;   // A stage [k][r], xor-swizzled
constexpr int SMB = 64 * 64;    // B stage [k][p], xor-swizzled
constexpr int SMM = 128 * 8;    // mask tile [r][8 t-slots]

// ---------------------------------------------------------------------------
// Fused split-K SGEMM. Grid (4 btiles, 63 kchunks), 128 threads.
// A[b,kk] = kk<K ? x*mask : (kk<KE ? mask[b,kk-K] : 0)      (on the fly)
// Bm[p,kk] = kk<K ? -2*proto : (kk<KE ? q[p,kk-K] : 0)      (on the fly)
// 128x64 C tile, 8x8 per thread.
// Swizzle: phys float4-group = group ^ (k>>2)  (stores ≤2-way, loads ~free)
// ---------------------------------------------------------------------------
__global__ __launch_bounds__(128) void gemm_kernel(const float* __restrict__ x,
                                                   const float* __restrict__ mask,
                                                   const float* __restrict__ proto) {
    extern __shared__ float sm[];
    float* smA = sm;
    float* smB = smA + SMA;
    float* mT  = smB + SMB;

    const int tid   = threadIdx.x;
    const int b0    = blockIdx.x * 128;
    const int kbase = blockIdx.y * KC;
    const int t0    = kbase / C;

    // mask tile: 8 t-slots cover the whole 64-k chunk's x-region
    for (int i = tid; i < 128 * 8; i += 128) {
        const int r = i >> 3, tt = i & 7, t = t0 + tt;
        mT[i] = (t < T) ? mask[(b0 + r) * T + t] : 0.f;
    }
    __syncthreads();

    const int k4l = tid & 15;           // float4 k-slot (local k = 4*k4l+j)
    const int rl  = tid >> 4;           // 0..7
    const int kk0 = kbase + k4l * 4;
    const bool fast = (kbase + KC <= K);   // chunks 0..56: pure x/proto region

    // ---- stage A (128 rows x 64 k)
    if (fast) {
        const int tA = kk0 / C - t0, tB = (kk0 + 1) / C - t0;
        const int tC2 = (kk0 + 2) / C - t0, tD = (kk0 + 3) / C - t0;
#pragma unroll
        for (int i = 0; i < 16; i++) {
            const int r = rl + 8 * i;
            const float* xp = x + (size_t)(b0 + r) * K + kk0;
            const float2 u = *(const float2*)xp;
            const float2 v = *(const float2*)(xp + 2);
            const float* m = mT + r * 8;
            float* d = smA + (k4l * 4) * 128 + ((((r >> 2) ^ k4l) << 2) | (r & 3));
            d[0]   = u.x * m[tA];
            d[128] = u.y * m[tB];
            d[256] = v.x * m[tC2];
            d[384] = v.y * m[tD];
        }
    } else {
#pragma unroll
        for (int i = 0; i < 16; i++) {
            const int r = rl + 8 * i;
            float* d = smA + (k4l * 4) * 128 + ((((r >> 2) ^ k4l) << 2) | (r & 3));
#pragma unroll
            for (int j = 0; j < 4; j++) {
                const int kk = kk0 + j;
                float v = 0.f;
                if (kk < K)
                    v = x[(size_t)(b0 + r) * K + kk] * mT[r * 8 + (kk / C - t0)];
                else if (kk < KE)
                    v = mask[(b0 + r) * T + (kk - K)];
                d[j * 128] = v;
            }
        }
    }

    // ---- stage B (64 p x 64 k)
    if (fast) {
#pragma unroll
        for (int i = 0; i < 8; i++) {
            const int p = rl + 8 * i;
            const float* pp = proto + (size_t)p * K + kk0;
            const float2 u = *(const float2*)pp;
            const float2 v = *(const float2*)(pp + 2);
            float* d = smB + (k4l * 4) * 64 + ((((p >> 2) ^ k4l) << 2) | (p & 3));
            d[0]   = -2.f * u.x;
            d[64]  = -2.f * u.y;
            d[128] = -2.f * v.x;
            d[192] = -2.f * v.y;
        }
    } else {
#pragma unroll
        for (int i = 0; i < 8; i++) {
            const int p = rl + 8 * i;
            float* d = smB + (k4l * 4) * 64 + ((((p >> 2) ^ k4l) << 2) | (p & 3));
#pragma unroll
            for (int j = 0; j < 4; j++) {
                const int kk = kk0 + j;
                float v = 0.f;
                if (kk < K) {
                    v = -2.f * proto[(size_t)p * K + kk];
                } else if (kk < KE) {
                    // q[p,t] = sum_c proto[p,t,c]^2, computed on the fly
                    const int t = kk - K;
                    const float* pr = proto + (size_t)p * K + t * C;
                    float s = 0.f;
#pragma unroll
                    for (int c = 0; c < C; c += 2) {
                        const float2 w = *(const float2*)(pr + c);
                        s = fmaf(w.x, w.x, fmaf(w.y, w.y, s));
                    }
                    v = s;
                }
                d[j * 64] = v;
            }
        }
    }
    __syncthreads();

    // ---- compute: 8x8 outer product, float4 swizzled LDS
    const int tx = tid & 7;     // p block: p = tx*8..+7
    const int ty = tid >> 3;    // r block: r = ty*8..+7
    float acc[8][8] = {};

#pragma unroll
    for (int k4 = 0; k4 < 16; k4++) {
        const int a0o = ((2 * ty)     ^ k4) << 2;
        const int a1o = ((2 * ty + 1) ^ k4) << 2;
        const int b0o = ((2 * tx)     ^ k4) << 2;
        const int b1o = ((2 * tx + 1) ^ k4) << 2;
#pragma unroll
        for (int j = 0; j < 4; j++) {
            const float* Ak = smA + (k4 * 4 + j) * 128;
            const float* Bk = smB + (k4 * 4 + j) * 64;
            const float4 a0 = *(const float4*)(Ak + a0o);
            const float4 a1 = *(const float4*)(Ak + a1o);
            const float4 bq0 = *(const float4*)(Bk + b0o);
            const float4 bq1 = *(const float4*)(Bk + b1o);
            const float av[8] = {a0.x, a0.y, a0.z, a0.w, a1.x, a1.y, a1.z, a1.w};
            const float bv[8] = {bq0.x, bq0.y, bq0.z, bq0.w,
                                 bq1.x, bq1.y, bq1.z, bq1.w};
#pragma unroll
            for (int ii = 0; ii < 8; ii++)
#pragma unroll
                for (int jj = 0; jj < 8; jj++)
                    acc[ii][jj] = fmaf(av[ii], bv[jj], acc[ii][jj]);
        }
    }

    // ---- partial stores
    float* dst = g_part + ((size_t)blockIdx.y * B + b0 + ty * 8) * P + tx * 8;
#pragma unroll
    for (int ii = 0; ii < 8; ii++) {
        *(float4*)(dst + (size_t)ii * P)     = make_float4(acc[ii][0], acc[ii][1],
                                                           acc[ii][2], acc[ii][3]);
        *(float4*)(dst + (size_t)ii * P + 4) = make_float4(acc[ii][4], acc[ii][5],
                                                           acc[ii][6], acc[ii][7]);
    }
}

// ---------------------------------------------------------------------------
// Per-sample finalize (one CTA per b, 256 threads).
// ---------------------------------------------------------------------------
__global__ __launch_bounds__(256) void final_kernel(
    const float* __restrict__ x, const float* __restrict__ mask,
    const int* __restrict__ label, const float* __restrict__ proto,
    float* __restrict__ out) {
    __shared__ float mk[T];
    __shared__ float red4[4][P];
    __shared__ float dist[P];
    __shared__ float wred[8];
    __shared__ int sidx;

    const int b = blockIdx.x, tid = threadIdx.x;

    for (int t = tid; t < T; t += 256) {
        const float m = mask[b * T + t];
        mk[t] = m;
        out[O5 + b * T + t] = m;
    }

    // split-K partial reduce: p = tid&63, kc stripe = tid>>6 (4 stripes)
    {
        const int p = tid & 63, h = tid >> 6;
        float s = 0.f;
        for (int kc = h; kc < NKC; kc += 4)
            s += g_part[(size_t)kc * B * P + b * P + p];
        red4[h][p] = s;
    }
    __syncthreads();

    // input_seq copy fused with x2 = sum m*x^2
    const float2* xr = (const float2*)(x + (size_t)b * K);
    float2* o1 = (float2*)(out + O1 + (size_t)b * K);
    float s = 0.f;
    for (int i = tid; i < K / 2; i += 256) {
        const float2 v = xr[i];
        o1[i] = v;
        s = fmaf(v.x * mk[(2 * i) / C], v.x, s);
        s = fmaf(v.y * mk[(2 * i + 1) / C], v.y, s);
    }
#pragma unroll
    for (int o = 16; o; o >>= 1) s += __shfl_down_sync(0xffffffffu, s, o);
    if ((tid & 31) == 0) wred[tid >> 5] = s;
    __syncthreads();
    float x2 = 0.f;
#pragma unroll
    for (int wsum = 0; wsum < 8; wsum++) x2 += wred[wsum];

    if (tid < P) {
        const float d = x2 + ((red4[0][tid] + red4[1][tid]) +
                              (red4[2][tid] + red4[3][tid]));
        dist[tid] = d;
        out[O2 + (size_t)b * P + tid] = d;
    }
    __syncthreads();

    // argmin, first-min tie-break (matches jnp.argmin)
    if (tid < 32) {
        float v0 = dist[tid], v1 = dist[tid + 32];
        float v; int ix;
        if (v1 < v0) { v = v1; ix = tid + 32; } else { v = v0; ix = tid; }
#pragma unroll
        for (int o = 16; o; o >>= 1) {
            const float ov = __shfl_down_sync(0xffffffffu, v, o);
            const int   oi = __shfl_down_sync(0xffffffffu, ix, o);
            if (ov < v || (ov == v && oi < ix)) { v = ov; ix = oi; }
        }
        if (tid == 0) {
            sidx = ix;
            out[O3 + b] = (float)ix;
            out[O4 + b] = (float)label[b];
        }
    }
    __syncthreads();

    const float2* pr = (const float2*)(proto + (size_t)sidx * K);
    float2* o0 = (float2*)(out + (size_t)b * K);
    for (int i = tid; i < K / 2; i += 256) o0[i] = pr[i];
}

// ---------------------------------------------------------------------------
extern "C" void kernel_launch(void* const* d_in, const int* in_sizes, int n_in,
                              void* d_out, int out_size) {
    (void)in_sizes; (void)n_in; (void)out_size;
    const float* x     = (const float*)d_in[0];
    const float* mask  = (const float*)d_in[1];
    const int*   label = (const int*)  d_in[2];
    const float* proto = (const float*)d_in[3];
    float* out = (float*)d_out;

    constexpr size_t GSM = (size_t)(SMA + SMB + SMM) * sizeof(float); // 53248 B
    cudaFuncSetAttribute(gemm_kernel,
                         cudaFuncAttributeMaxDynamicSharedMemorySize, (int)GSM);

    gemm_kernel<<<dim3(4, NKC), 128, GSM>>>(x, mask, proto);
    final_kernel<<<B, 256>>>(x, mask, label, proto, out);
}

// round 8
// speedup vs baseline: 1.0059x; 1.0059x over previous
#include <cuda_runtime.h>

// Problem constants
constexpr int B = 512, T = 365, C = 10, P = 64;
constexpr int K  = T * C;       // 3650
constexpr int KE = K + T;       // 4015
constexpr int KC  = 128;        // k per chunk (two 64-k stages)
constexpr int NKC = 32;         // chunks cover [0, 4096) ⊇ KE

// Output layout: [output_seq BK][input_seq BK][distances BP][indices B][label B][mask BT]
constexpr int O1 = B * K;
constexpr int O2 = O1 + B * K;
constexpr int O3 = O2 + B * P;
constexpr int O4 = O3 + B;
constexpr int O5 = O4 + B;

__device__ float g_part[NKC * B * P];   // split-K partials (4 MB, L2)
__device__ int   g_idx[B];

// smem (floats): two 64-k stages, xor-swizzled [k][dim]
constexpr int SMA = 2 * 64 * 128;
constexpr int SMB = 2 * 64 * 64;
constexpr int SMM = 128 * 16;           // mask tile [r][16 t-slots]

// ---------------------------------------------------------------------------
// Fused split-K SGEMM. Grid (4 btiles, 32 kchunks) = 128 CTAs, 256 threads.
// A[b,kk] = kk<K ? x*mask : (kk<KE ? mask[b,kk-K] : 0)
// Bm[p,kk] = kk<K ? -2*proto : (kk<KE ? q[p,kk-K] : 0)      (all on the fly)
// 128x64 C tile, 4x8 per thread, double-buffered.
// Swizzle: phys float4-group = group ^ (k>>2 & 15).
// ---------------------------------------------------------------------------
__global__ __launch_bounds__(256) void gemm_kernel(const float* __restrict__ x,
                                                   const float* __restrict__ mask,
                                                   const float* __restrict__ proto) {
    extern __shared__ float sm[];
    float* smA = sm;            // [2][64][128]
    float* smB = smA + SMA;     // [2][64][64]
    float* mT  = smB + SMB;     // [128][16]

    const int tid   = threadIdx.x;
    const int b0    = blockIdx.x * 128;
    const int kbase = blockIdx.y * KC;
    const int t0    = kbase / C;

    // mask tile: 16 t-slots cover the 128-k chunk's x-region
    for (int i = tid; i < 128 * 16; i += 256) {
        const int r = i >> 4, tt = i & 15, t = t0 + tt;
        mT[i] = (t < T) ? mask[(b0 + r) * T + t] : 0.f;
    }
    __syncthreads();

    const int k4l  = tid & 15;      // float4 k-slot within 64-k stage
    const int rgrp = tid >> 4;      // 0..15

    float4 va[8], vb[4];

    auto loadA = [&](int s) {
        const int kk0 = kbase + s * 64 + k4l * 4;
        if (kk0 + 63 < K || kk0 + 3 < K) { /* per-slot fast check below */ }
        if (kk0 + 3 < K) {
            const int tA = kk0 / C - t0, tB = (kk0 + 1) / C - t0;
            const int tC2 = (kk0 + 2) / C - t0, tD = (kk0 + 3) / C - t0;
#pragma unroll
            for (int i = 0; i < 8; i++) {
                const int r = rgrp + 16 * i;
                const float* xp = x + (size_t)(b0 + r) * K + kk0;
                const float2 u = *(const float2*)xp;
                const float2 v = *(const float2*)(xp + 2);
                const float* m = mT + r * 16;
                va[i] = make_float4(u.x * m[tA], u.y * m[tB],
                                    v.x * m[tC2], v.y * m[tD]);
            }
        } else {
#pragma unroll
            for (int i = 0; i < 8; i++) {
                const int r = rgrp + 16 * i;
                float w[4];
#pragma unroll
                for (int j = 0; j < 4; j++) {
                    const int kk = kk0 + j;
                    float v = 0.f;
                    if (kk < K)
                        v = x[(size_t)(b0 + r) * K + kk] * mT[r * 16 + (kk / C - t0)];
                    else if (kk < KE)
                        v = mask[(b0 + r) * T + (kk - K)];
                    w[j] = v;
                }
                va[i] = make_float4(w[0], w[1], w[2], w[3]);
            }
        }
    };
    auto storeA = [&](int s) {
        float* base = smA + (s * 64 + k4l * 4) * 128;
#pragma unroll
        for (int i = 0; i < 8; i++) {
            const int r = rgrp + 16 * i;
            float* d = base + ((((r >> 2) ^ k4l) << 2) | (r & 3));
            d[0]   = va[i].x;
            d[128] = va[i].y;
            d[256] = va[i].z;
            d[384] = va[i].w;
        }
    };
    auto loadB = [&](int s) {
        const int kk0 = kbase + s * 64 + k4l * 4;
        if (kk0 + 3 < K) {
#pragma unroll
            for (int i = 0; i < 4; i++) {
                const int p = rgrp + 16 * i;
                const float* pp = proto + (size_t)p * K + kk0;
                const float2 u = *(const float2*)pp;
                const float2 v = *(const float2*)(pp + 2);
                vb[i] = make_float4(-2.f * u.x, -2.f * u.y, -2.f * v.x, -2.f * v.y);
            }
        } else {
#pragma unroll
            for (int i = 0; i < 4; i++) {
                const int p = rgrp + 16 * i;
                float w[4];
#pragma unroll
                for (int j = 0; j < 4; j++) {
                    const int kk = kk0 + j;
                    float v = 0.f;
                    if (kk < K) {
                        v = -2.f * proto[(size_t)p * K + kk];
                    } else if (kk < KE) {
                        const int t = kk - K;
                        const float* pr = proto + (size_t)p * K + t * C;
                        float s2 = 0.f;
#pragma unroll
                        for (int c = 0; c < C; c += 2) {
                            const float2 q2 = *(const float2*)(pr + c);
                            s2 = fmaf(q2.x, q2.x, fmaf(q2.y, q2.y, s2));
                        }
                        v = s2;
                    }
                    w[j] = v;
                }
                vb[i] = make_float4(w[0], w[1], w[2], w[3]);
            }
        }
    };
    auto storeB = [&](int s) {
        float* base = smB + (s * 64 + k4l * 4) * 64;
#pragma unroll
        for (int i = 0; i < 4; i++) {
            const int p = rgrp + 16 * i;
            float* d = base + ((((p >> 2) ^ k4l) << 2) | (p & 3));
            d[0]   = vb[i].x;
            d[64]  = vb[i].y;
            d[128] = vb[i].z;
            d[192] = vb[i].w;
        }
    };

    const int tx = tid & 7;     // p: tx*8..+7 (two float4 groups 2tx, 2tx+1)
    const int ty = tid >> 3;    // r: ty*4..+3 (one float4 group ty)
    float acc[4][8] = {};

    auto compute = [&](int s) {
#pragma unroll 8
        for (int k = 0; k < 64; k++) {
            const int k4 = k >> 2;
            const float* Ak = smA + (s * 64 + k) * 128;
            const float* Bk = smB + (s * 64 + k) * 64;
            const float4 a  = *(const float4*)(Ak + ((ty ^ k4) << 2));
            const float4 bq0 = *(const float4*)(Bk + (((2 * tx) ^ k4) << 2));
            const float4 bq1 = *(const float4*)(Bk + (((2 * tx + 1) ^ k4) << 2));
            const float av[4] = {a.x, a.y, a.z, a.w};
            const float bv[8] = {bq0.x, bq0.y, bq0.z, bq0.w,
                                 bq1.x, bq1.y, bq1.z, bq1.w};
#pragma unroll
            for (int ii = 0; ii < 4; ii++)
#pragma unroll
                for (int jj = 0; jj < 8; jj++)
                    acc[ii][jj] = fmaf(av[ii], bv[jj], acc[ii][jj]);
        }
    };

    // double-buffered pipeline over the 128-k chunk
    loadA(0); loadB(0);
    storeA(0); storeB(0);
    __syncthreads();
    loadA(1); loadB(1);      // LDGs in flight during compute(0)
    compute(0);
    storeA(1); storeB(1);
    __syncthreads();
    compute(1);

    float* dst = g_part + ((size_t)blockIdx.y * B + b0 + ty * 4) * P + tx * 8;
#pragma unroll
    for (int ii = 0; ii < 4; ii++) {
        *(float4*)(dst + (size_t)ii * P)     = make_float4(acc[ii][0], acc[ii][1],
                                                           acc[ii][2], acc[ii][3]);
        *(float4*)(dst + (size_t)ii * P + 4) = make_float4(acc[ii][4], acc[ii][5],
                                                           acc[ii][6], acc[ii][7]);
    }
}

// ---------------------------------------------------------------------------
// F1: per-sample distances + argmin (one CTA per b, 256 threads). No copies.
// ---------------------------------------------------------------------------
__global__ __launch_bounds__(256) void dist_kernel(
    const float* __restrict__ x, const float* __restrict__ mask,
    const int* __restrict__ label, float* __restrict__ out) {
    __shared__ float mk[T];
    __shared__ float red4[4][P];
    __shared__ float dist[P];
    __shared__ float wred[8];

    const int b = blockIdx.x, tid = threadIdx.x;

    for (int t = tid; t < T; t += 256) mk[t] = mask[b * T + t];

    // split-K reduce: p = tid&63, stripe h = tid>>6 (8 chunks each)
    {
        const int p = tid & 63, h = tid >> 6;
        float s = 0.f;
#pragma unroll
        for (int kc = 8 * h; kc < 8 * h + 8; kc++)
            s += g_part[(size_t)kc * B * P + b * P + p];
        red4[h][p] = s;
    }
    __syncthreads();

    // x2 = sum m*x^2
    const float2* xr = (const float2*)(x + (size_t)b * K);
    float s = 0.f;
    for (int i = tid; i < K / 2; i += 256) {
        const float2 v = xr[i];
        s = fmaf(v.x * mk[(2 * i) / C], v.x, s);
        s = fmaf(v.y * mk[(2 * i + 1) / C], v.y, s);
    }
#pragma unroll
    for (int o = 16; o; o >>= 1) s += __shfl_down_sync(0xffffffffu, s, o);
    if ((tid & 31) == 0) wred[tid >> 5] = s;
    __syncthreads();
    float x2 = 0.f;
#pragma unroll
    for (int wsum = 0; wsum < 8; wsum++) x2 += wred[wsum];

    if (tid < P) {
        const float d = x2 + ((red4[0][tid] + red4[1][tid]) +
                              (red4[2][tid] + red4[3][tid]));
        dist[tid] = d;
        out[O2 + (size_t)b * P + tid] = d;
    }
    __syncthreads();

    // argmin, first-min tie-break (matches jnp.argmin)
    if (tid < 32) {
        float v0 = dist[tid], v1 = dist[tid + 32];
        float v; int ix;
        if (v1 < v0) { v = v1; ix = tid + 32; } else { v = v0; ix = tid; }
#pragma unroll
        for (int o = 16; o; o >>= 1) {
            const float ov = __shfl_down_sync(0xffffffffu, v, o);
            const int   oi = __shfl_down_sync(0xffffffffu, ix, o);
            if (ov < v || (ov == v && oi < ix)) { v = ov; ix = oi; }
        }
        if (tid == 0) {
            g_idx[b] = ix;
            out[O3 + b] = (float)ix;
            out[O4 + b] = (float)label[b];
        }
    }
}

// ---------------------------------------------------------------------------
// F2: gather selected prototype (one CTA per b).
// ---------------------------------------------------------------------------
__global__ __launch_bounds__(256) void gather_kernel(const float* __restrict__ proto,
                                                     float* __restrict__ out) {
    const int b = blockIdx.x, tid = threadIdx.x;
    const float2* pr = (const float2*)(proto + (size_t)g_idx[b] * K);
    float2* o0 = (float2*)(out + (size_t)b * K);
    for (int i = tid; i < K / 2; i += 256) o0[i] = pr[i];
}

// ---------------------------------------------------------------------------
extern "C" void kernel_launch(void* const* d_in, const int* in_sizes, int n_in,
                              void* d_out, int out_size) {
    (void)in_sizes; (void)n_in; (void)out_size;
    const float* x     = (const float*)d_in[0];
    const float* mask  = (const float*)d_in[1];
    const int*   label = (const int*)  d_in[2];
    const float* proto = (const float*)d_in[3];
    float* out = (float*)d_out;

    constexpr size_t GSM = (size_t)(SMA + SMB + SMM) * sizeof(float); // 106496 B
    cudaFuncSetAttribute(gemm_kernel,
                         cudaFuncAttributeMaxDynamicSharedMemorySize, (int)GSM);

    gemm_kernel<<<dim3(4, NKC), 256, GSM>>>(x, mask, proto);
    dist_kernel<<<B, 256>>>(x, mask, label, out);
    // bulk copies: device-to-device async memcpy (graph-capturable)
    cudaMemcpyAsync(out + O1, x,    (size_t)B * K * sizeof(float),
                    cudaMemcpyDeviceToDevice);
    cudaMemcpyAsync(out + O5, mask, (size_t)B * T * sizeof(float),
                    cudaMemcpyDeviceToDevice);
    gather_kernel<<<B, 256>>>(proto, out);
}

// round 9
// speedup vs baseline: 1.1033x; 1.0969x over previous
#include <cuda_runtime.h>

// Problem constants
constexpr int B = 512, T = 365, C = 10, P = 64;
constexpr int K  = T * C;       // 3650
constexpr int KE = K + T;       // 4015
constexpr int KC  = 64;         // k per chunk (two 32-k stages)
constexpr int NKC = 63;         // chunks cover [0, 4032) ⊇ KE

// Output layout: [output_seq BK][input_seq BK][distances BP][indices B][label B][mask BT]
constexpr int O1 = B * K;
constexpr int O2 = O1 + B * K;
constexpr int O3 = O2 + B * P;
constexpr int O4 = O3 + B;
constexpr int O5 = O4 + B;

__device__ float g_part[NKC * B * P];   // split-K partials (~8.3 MB, L2)
__device__ int   g_idx[B];

// smem (floats): two 32-k stages, xor-swizzled [k][col], col' = col ^ (k4<<2)
constexpr int SMA = 2 * 32 * 128;   // 32 KB
constexpr int SMB = 2 * 32 * 64;    // 16 KB
constexpr int SMM = 128 * 8;        //  4 KB mask tile [r][8 t-slots]

// ---------------------------------------------------------------------------
// Fused split-K SGEMM. Grid (4 btiles, 63 kchunks) = 252 CTAs, 256 threads,
// 52 KB smem -> 2 CTAs/SM (16 warps/SM).
// A[b,kk] = kk<K ? x*mask : (kk<KE ? mask[b,kk-K] : 0)
// Bm[p,kk] = kk<K ? -2*proto : (kk<KE ? q[p,kk-K] : 0)     (all on the fly)
// 128x64 C tile, 4x8 per thread, double-buffered.
// ---------------------------------------------------------------------------
__global__ __launch_bounds__(256, 2) void gemm_kernel(const float* __restrict__ x,
                                                      const float* __restrict__ mask,
                                                      const float* __restrict__ proto) {
    extern __shared__ float sm[];
    float* smA = sm;            // [2][32][128]
    float* smB = smA + SMA;     // [2][32][64]
    float* mT  = smB + SMB;     // [128][8]

    const int tid   = threadIdx.x;
    const int b0    = blockIdx.x * 128;
    const int kbase = blockIdx.y * KC;
    const int t0    = kbase / C;

    // mask tile: 8 t-slots cover the 64-k chunk's x-region
    for (int i = tid; i < 128 * 8; i += 256) {
        const int r = i >> 3, tt = i & 7, t = t0 + tt;
        mT[i] = (t < T) ? mask[(b0 + r) * T + t] : 0.f;
    }
    __syncthreads();

    const int k4l  = tid & 7;       // float4 k-slot within 32-k stage (0..7)
    const int rgrp = tid >> 3;      // 0..31

    float4 va[4], vb[2];

    auto loadA = [&](int s) {
        const int kk0 = kbase + s * 32 + k4l * 4;
        if (kk0 + 3 < K) {
            const int tA = kk0 / C - t0, tB = (kk0 + 1) / C - t0;
            const int tC2 = (kk0 + 2) / C - t0, tD = (kk0 + 3) / C - t0;
#pragma unroll
            for (int i = 0; i < 4; i++) {
                const int r = rgrp + 32 * i;
                const float* xp = x + (size_t)(b0 + r) * K + kk0;
                const float2 u = *(const float2*)xp;
                const float2 v = *(const float2*)(xp + 2);
                const float* m = mT + r * 8;
                va[i] = make_float4(u.x * m[tA], u.y * m[tB],
                                    v.x * m[tC2], v.y * m[tD]);
            }
        } else {
#pragma unroll
            for (int i = 0; i < 4; i++) {
                const int r = rgrp + 32 * i;
                float w[4];
#pragma unroll
                for (int j = 0; j < 4; j++) {
                    const int kk = kk0 + j;
                    float v = 0.f;
                    if (kk < K)
                        v = x[(size_t)(b0 + r) * K + kk] * mT[r * 8 + (kk / C - t0)];
                    else if (kk < KE)
                        v = mask[(b0 + r) * T + (kk - K)];
                    w[j] = v;
                }
                va[i] = make_float4(w[0], w[1], w[2], w[3]);
            }
        }
    };
    auto storeA = [&](int s) {
        float* base = smA + (s * 32 + k4l * 4) * 128;
        const int sw = k4l << 2;
#pragma unroll
        for (int i = 0; i < 4; i++) {
            const int pc = (rgrp + 32 * i) ^ sw;    // conflict-free across warp
            base[pc]       = va[i].x;
            base[128 + pc] = va[i].y;
            base[256 + pc] = va[i].z;
            base[384 + pc] = va[i].w;
        }
    };
    auto loadB = [&](int s) {
        const int kk0 = kbase + s * 32 + k4l * 4;
        if (kk0 + 3 < K) {
#pragma unroll
            for (int i = 0; i < 2; i++) {
                const int p = rgrp + 32 * i;
                const float* pp = proto + (size_t)p * K + kk0;
                const float2 u = *(const float2*)pp;
                const float2 v = *(const float2*)(pp + 2);
                vb[i] = make_float4(-2.f * u.x, -2.f * u.y, -2.f * v.x, -2.f * v.y);
            }
        } else {
#pragma unroll
            for (int i = 0; i < 2; i++) {
                const int p = rgrp + 32 * i;
                float w[4];
#pragma unroll
                for (int j = 0; j < 4; j++) {
                    const int kk = kk0 + j;
                    float v = 0.f;
                    if (kk < K) {
                        v = -2.f * proto[(size_t)p * K + kk];
                    } else if (kk < KE) {
                        const int t = kk - K;
                        const float* pr = proto + (size_t)p * K + t * C;
                        float s2 = 0.f;
#pragma unroll
                        for (int c = 0; c < C; c += 2) {
                            const float2 q2 = *(const float2*)(pr + c);
                            s2 = fmaf(q2.x, q2.x, fmaf(q2.y, q2.y, s2));
                        }
                        v = s2;
                    }
                    w[j] = v;
                }
                vb[i] = make_float4(w[0], w[1], w[2], w[3]);
            }
        }
    };
    auto storeB = [&](int s) {
        float* base = smB + (s * 32 + k4l * 4) * 64;
        const int sw = k4l << 2;
#pragma unroll
        for (int i = 0; i < 2; i++) {
            const int pc = (rgrp + 32 * i) ^ sw;
            base[pc]       = vb[i].x;
            base[64 + pc]  = vb[i].y;
            base[128 + pc] = vb[i].z;
            base[192 + pc] = vb[i].w;
        }
    };

    const int tx = tid & 7;     // p: tx*8..+7
    const int ty = tid >> 3;    // b-rows: ty*4..+3
    float acc[4][8] = {};

    auto compute = [&](int s) {
        const float* As = smA + s * 32 * 128;
        const float* Bs = smB + s * 32 * 64;
#pragma unroll
        for (int k4 = 0; k4 < 8; k4++) {
            const float4* A0 = (const float4*)(As + k4 * 4 * 128);
            const float4* B0 = (const float4*)(Bs + k4 * 4 * 64);
            const int ga  = ty ^ k4;
            const int gb0 = (2 * tx) ^ k4;
            const int gb1 = (2 * tx + 1) ^ k4;
#pragma unroll
            for (int j = 0; j < 4; j++) {
                const float4 a  = A0[j * 32 + ga];
                const float4 q0 = B0[j * 16 + gb0];
                const float4 q1 = B0[j * 16 + gb1];
                const float av[4] = {a.x, a.y, a.z, a.w};
                const float bv[8] = {q0.x, q0.y, q0.z, q0.w, q1.x, q1.y, q1.z, q1.w};
#pragma unroll
                for (int e = 0; e < 4; e++)
#pragma unroll
                    for (int jj = 0; jj < 8; jj++)
                        acc[e][jj] = fmaf(av[e], bv[jj], acc[e][jj]);
            }
        }
    };

    // double-buffered pipeline over the 64-k chunk
    loadA(0); loadB(0);
    storeA(0); storeB(0);
    __syncthreads();
    loadA(1); loadB(1);      // LDGs in flight during compute(0)
    compute(0);
    storeA(1); storeB(1);
    __syncthreads();
    compute(1);

    // partial stores (rows 4ty..4ty+3, cols 8tx..8tx+7)
    float* dst = g_part + ((size_t)blockIdx.y * B + b0 + ty * 4) * P + tx * 8;
#pragma unroll
    for (int e = 0; e < 4; e++) {
        *(float4*)(dst + (size_t)e * P)     = make_float4(acc[e][0], acc[e][1],
                                                          acc[e][2], acc[e][3]);
        *(float4*)(dst + (size_t)e * P + 4) = make_float4(acc[e][4], acc[e][5],
                                                          acc[e][6], acc[e][7]);
    }
}

// ---------------------------------------------------------------------------
// F1: per-sample distances + argmin (one CTA per b, 256 threads).
// ---------------------------------------------------------------------------
__global__ __launch_bounds__(256) void dist_kernel(
    const float* __restrict__ x, const float* __restrict__ mask,
    const int* __restrict__ label, float* __restrict__ out) {
    __shared__ float mk[T];
    __shared__ float red4[4][P];
    __shared__ float dist[P];
    __shared__ float wred[8];

    const int b = blockIdx.x, tid = threadIdx.x;

    for (int t = tid; t < T; t += 256) mk[t] = mask[b * T + t];

    // split-K reduce: p = tid&63, stripe h = tid>>6
    {
        const int p = tid & 63, h = tid >> 6;
        float s = 0.f;
        for (int kc = h; kc < NKC; kc += 4)
            s += g_part[(size_t)kc * B * P + b * P + p];
        red4[h][p] = s;
    }
    __syncthreads();

    // x2 = sum m*x^2
    const float2* xr = (const float2*)(x + (size_t)b * K);
    float s = 0.f;
    for (int i = tid; i < K / 2; i += 256) {
        const float2 v = xr[i];
        s = fmaf(v.x * mk[(2 * i) / C], v.x, s);
        s = fmaf(v.y * mk[(2 * i + 1) / C], v.y, s);
    }
#pragma unroll
    for (int o = 16; o; o >>= 1) s += __shfl_down_sync(0xffffffffu, s, o);
    if ((tid & 31) == 0) wred[tid >> 5] = s;
    __syncthreads();
    float x2 = 0.f;
#pragma unroll
    for (int wsum = 0; wsum < 8; wsum++) x2 += wred[wsum];

    if (tid < P) {
        const float d = x2 + ((red4[0][tid] + red4[1][tid]) +
                              (red4[2][tid] + red4[3][tid]));
        dist[tid] = d;
        out[O2 + (size_t)b * P + tid] = d;
    }
    __syncthreads();

    // argmin, first-min tie-break (matches jnp.argmin)
    if (tid < 32) {
        float v0 = dist[tid], v1 = dist[tid + 32];
        float v; int ix;
        if (v1 < v0) { v = v1; ix = tid + 32; } else { v = v0; ix = tid; }
#pragma unroll
        for (int o = 16; o; o >>= 1) {
            const float ov = __shfl_down_sync(0xffffffffu, v, o);
            const int   oi = __shfl_down_sync(0xffffffffu, ix, o);
            if (ov < v || (ov == v && oi < ix)) { v = ov; ix = oi; }
        }
        if (tid == 0) {
            g_idx[b] = ix;
            out[O3 + b] = (float)ix;
            out[O4 + b] = (float)label[b];
        }
    }
}

// ---------------------------------------------------------------------------
// F2: gather selected prototype (one CTA per b).
// ---------------------------------------------------------------------------
__global__ __launch_bounds__(256) void gather_kernel(const float* __restrict__ proto,
                                                     float* __restrict__ out) {
    const int b = blockIdx.x, tid = threadIdx.x;
    const float2* pr = (const float2*)(proto + (size_t)g_idx[b] * K);
    float2* o0 = (float2*)(out + (size_t)b * K);
    for (int i = tid; i < K / 2; i += 256) o0[i] = pr[i];
}

// ---------------------------------------------------------------------------
extern "C" void kernel_launch(void* const* d_in, const int* in_sizes, int n_in,
                              void* d_out, int out_size) {
    (void)in_sizes; (void)n_in; (void)out_size;
    const float* x     = (const float*)d_in[0];
    const float* mask  = (const float*)d_in[1];
    const int*   label = (const int*)  d_in[2];
    const float* proto = (const float*)d_in[3];
    float* out = (float*)d_out;

    constexpr size_t GSM = (size_t)(SMA + SMB + SMM) * sizeof(float); // 53248 B
    cudaFuncSetAttribute(gemm_kernel,
                         cudaFuncAttributeMaxDynamicSharedMemorySize, (int)GSM);

    gemm_kernel<<<dim3(4, NKC), 256, GSM>>>(x, mask, proto);
    dist_kernel<<<B, 256>>>(x, mask, label, out);
    // bulk copies: device-to-device async memcpy (graph-capturable)
    cudaMemcpyAsync(out + O1, x,    (size_t)B * K * sizeof(float),
                    cudaMemcpyDeviceToDevice);
    cudaMemcpyAsync(out + O5, mask, (size_t)B * T * sizeof(float),
                    cudaMemcpyDeviceToDevice);
    gather_kernel<<<B, 256>>>(proto, out);
}

// round 11
// speedup vs baseline: 1.2293x; 1.1142x over previous
#include <cuda_runtime.h>

// Problem constants
constexpr int B = 512, T = 365, C = 10, P = 64;
constexpr int K  = T * C;       // 3650
constexpr int KE = K + T;       // 4015
constexpr int KC  = 64;         // k per CTA chunk (4 stages of 16)
constexpr int NKC = 63;         // chunks cover [0, 4032) ⊇ KE

// Output layout: [output_seq BK][input_seq BK][distances BP][indices B][label B][mask BT]
constexpr int O1 = B * K;
constexpr int O2 = O1 + B * K;
constexpr int O3 = O2 + B * P;
constexpr int O4 = O3 + B;
constexpr int O5 = O4 + B;

__device__ float g_part[NKC * B * P];   // split-K partials (~8.3 MB, L2)

// ---------------------------------------------------------------------------
// Fused split-K SGEMM. Grid (8 btiles, 63 kchunks) = 504 CTAs, 128 threads,
// 18 KB smem, ~75 regs -> 4-6 CTAs/SM.
// A[b,kk] = kk<K ? x*mask : (kk<KE ? mask[b,kk-K] : 0)
// Bm[p,kk] = kk<K ? -2*proto : (kk<KE ? q[p,kk-K] : 0)     (all on the fly)
// 64x64 C tile, 4x8 per thread. 4-stage (16-k) rolling pipeline, 2 smem bufs.
// smem [k][col] with float-level swizzle col' = col ^ (k4<<3):
//   transpose STS conflict-free; compute LDS.128 one wavefront each.
// ---------------------------------------------------------------------------
__global__ __launch_bounds__(128) void gemm_kernel(const float* __restrict__ x,
                                                   const float* __restrict__ mask,
                                                   const float* __restrict__ proto) {
    __shared__ float smA[2 * 16 * 64];
    __shared__ float smB[2 * 16 * 64];
    __shared__ float mT[64 * 8];

    const int tid   = threadIdx.x;
    const int b0    = blockIdx.x * 64;
    const int kbase = blockIdx.y * KC;
    const int t0    = kbase / C;

    // mask tile: 8 t-slots cover this 64-k chunk's x-region
    for (int i = tid; i < 64 * 8; i += 128) {
        const int r = i >> 3, tt = i & 7, t = t0 + tt;
        mT[i] = (t < T) ? mask[(b0 + r) * T + t] : 0.f;
    }
    __syncthreads();

    const int k4 = tid & 3;     // float4 k-slot within 16-k stage
    const int rr = tid >> 2;    // 0..31 (rows rr, rr+32)

    float4 va[2], vb[2];

    auto loadA = [&](int s) {
        const int kk0 = kbase + s * 16 + k4 * 4;
        if (kk0 + 3 < K) {
            const int tA = kk0 / C - t0, tB = (kk0 + 1) / C - t0;
            const int tC2 = (kk0 + 2) / C - t0, tD = (kk0 + 3) / C - t0;
#pragma unroll
            for (int i = 0; i < 2; i++) {
                const int r = rr + 32 * i;
                const float* xp = x + (size_t)(b0 + r) * K + kk0;
                const float2 u = *(const float2*)xp;
                const float2 v = *(const float2*)(xp + 2);
                const float* m = mT + r * 8;
                va[i] = make_float4(u.x * m[tA], u.y * m[tB],
                                    v.x * m[tC2], v.y * m[tD]);
            }
        } else {
#pragma unroll
            for (int i = 0; i < 2; i++) {
                const int r = rr + 32 * i;
                float w[4];
#pragma unroll
                for (int j = 0; j < 4; j++) {
                    const int kk = kk0 + j;
                    float v = 0.f;
                    if (kk < K)
                        v = x[(size_t)(b0 + r) * K + kk] * mT[r * 8 + (kk / C - t0)];
                    else if (kk < KE)
                        v = mask[(b0 + r) * T + (kk - K)];
                    w[j] = v;
                }
                va[i] = make_float4(w[0], w[1], w[2], w[3]);
            }
        }
    };
    auto loadB = [&](int s) {
        const int kk0 = kbase + s * 16 + k4 * 4;
        if (kk0 + 3 < K) {
#pragma unroll
            for (int i = 0; i < 2; i++) {
                const int p = rr + 32 * i;
                const float* pp = proto + (size_t)p * K + kk0;
                const float2 u = *(const float2*)pp;
                const float2 v = *(const float2*)(pp + 2);
                vb[i] = make_float4(-2.f * u.x, -2.f * u.y, -2.f * v.x, -2.f * v.y);
            }
        } else {
#pragma unroll
            for (int i = 0; i < 2; i++) {
                const int p = rr + 32 * i;
                float w[4];
#pragma unroll
                for (int j = 0; j < 4; j++) {
                    const int kk = kk0 + j;
                    float v = 0.f;
                    if (kk < K) {
                        v = -2.f * proto[(size_t)p * K + kk];
                    } else if (kk < KE) {
                        const int t = kk - K;
                        const float* pr = proto + (size_t)p * K + t * C;
                        float s2 = 0.f;
#pragma unroll
                        for (int c = 0; c < C; c += 2) {
                            const float2 q2 = *(const float2*)(pr + c);
                            s2 = fmaf(q2.x, q2.x, fmaf(q2.y, q2.y, s2));
                        }
                        v = s2;
                    }
                    w[j] = v;
                }
                vb[i] = make_float4(w[0], w[1], w[2], w[3]);
            }
        }
    };

    const int cs = k4 << 3;     // store swizzle (float level, bits 3-4)
    auto storeA = [&](int s) {
        float* base = smA + (s & 1) * 1024 + (k4 * 4) * 64;
#pragma unroll
        for (int i = 0; i < 2; i++) {
            const int col = (rr + 32 * i) ^ cs;
            base[col]       = va[i].x;
            base[64 + col]  = va[i].y;
            base[128 + col] = va[i].z;
            base[192 + col] = va[i].w;
        }
    };
    auto storeB = [&](int s) {
        float* base = smB + (s & 1) * 1024 + (k4 * 4) * 64;
#pragma unroll
        for (int i = 0; i < 2; i++) {
            const int col = (rr + 32 * i) ^ cs;
            base[col]       = vb[i].x;
            base[64 + col]  = vb[i].y;
            base[128 + col] = vb[i].z;
            base[192 + col] = vb[i].w;
        }
    };

    const int tx = tid & 7;     // p: 8tx..8tx+7
    const int ty = tid >> 3;    // m: 4ty..4ty+3
    float acc[4][8] = {};

    auto compute = [&](int s) {
        const float* As = smA + (s & 1) * 1024;
        const float* Bs = smB + (s & 1) * 1024;
#pragma unroll
        for (int k = 0; k < 16; k++) {
            const int sw = (k >> 2) << 1;           // float4-level swizzle
            const float4 a  = ((const float4*)(As + k * 64))[ty ^ sw];
            const float4 q0 = ((const float4*)(Bs + k * 64))[(2 * tx) ^ sw];
            const float4 q1 = ((const float4*)(Bs + k * 64))[(2 * tx + 1) ^ sw];
            const float av[4] = {a.x, a.y, a.z, a.w};
            const float bv[8] = {q0.x, q0.y, q0.z, q0.w, q1.x, q1.y, q1.z, q1.w};
#pragma unroll
            for (int e = 0; e < 4; e++)
#pragma unroll
                for (int jj = 0; jj < 8; jj++)
                    acc[e][jj] = fmaf(av[e], bv[jj], acc[e][jj]);
        }
    };

    // 4-stage rolling pipeline, 2 smem buffers
    loadA(0); loadB(0);
    storeA(0); storeB(0);
    loadA(1); loadB(1);
    __syncthreads();
#pragma unroll
    for (int s = 0; s < 4; s++) {
        if (s + 1 < 4) { storeA(s + 1); storeB(s + 1); }
        if (s + 2 < 4) { loadA(s + 2); loadB(s + 2); }
        compute(s);
        __syncthreads();
    }

    // partial stores (rows 4ty..+3, cols 8tx..+7)
    float* dst = g_part + ((size_t)blockIdx.y * B + b0 + ty * 4) * P + tx * 8;
#pragma unroll
    for (int e = 0; e < 4; e++) {
        *(float4*)(dst + (size_t)e * P)     = make_float4(acc[e][0], acc[e][1],
                                                          acc[e][2], acc[e][3]);
        *(float4*)(dst + (size_t)e * P + 4) = make_float4(acc[e][4], acc[e][5],
                                                          acc[e][6], acc[e][7]);
    }
}

// ---------------------------------------------------------------------------
// Epilogue: grid 768. Blocks <512: per-sample distances+argmin+gather+label.
// Blocks >=512: grid-stride copies of input_seq and mask.
// ---------------------------------------------------------------------------
constexpr int NCPY = 256;

__global__ __launch_bounds__(256) void epi_kernel(
    const float* __restrict__ x, const float* __restrict__ mask,
    const int* __restrict__ label, const float* __restrict__ proto,
    float* __restrict__ out) {
    const int tid = threadIdx.x;

    if (blockIdx.x >= B) {
        // ---- copy lane
        const int cid = blockIdx.x - B;
        const int gsz = NCPY * 256;
        const int g   = cid * 256 + tid;
        const float2* x2p = (const float2*)x;
        float2* o1 = (float2*)(out + O1);
        for (int i = g; i < B * K / 2; i += gsz) o1[i] = x2p[i];
        const float4* m4 = (const float4*)mask;
        float4* o5 = (float4*)(out + O5);
        for (int i = g; i < B * T / 4; i += gsz) o5[i] = m4[i];
        return;
    }

    // ---- distance lane (one CTA per sample)
    __shared__ float mk[T];
    __shared__ float red[4][P];
    __shared__ float dist[P];
    __shared__ float wred[8];
    __shared__ int sidx;

    const int b = blockIdx.x;

    for (int t = tid; t < T; t += 256) mk[t] = mask[b * T + t];

    // split-K reduce: p = tid&63, stripe h = tid>>6
    {
        const int p = tid & 63, h = tid >> 6;
        float s = 0.f;
        for (int kc = h; kc < NKC; kc += 4)
            s += g_part[(size_t)kc * B * P + b * P + p];
        red[h][p] = s;
    }
    __syncthreads();

    // x2 = sum m*x^2
    const float2* xr = (const float2*)(x + (size_t)b * K);
    float s = 0.f;
    for (int i = tid; i < K / 2; i += 256) {
        const float2 v = xr[i];
        s = fmaf(v.x * mk[(2 * i) / C], v.x, s);
        s = fmaf(v.y * mk[(2 * i + 1) / C], v.y, s);
    }
#pragma unroll
    for (int o = 16; o; o >>= 1) s += __shfl_down_sync(0xffffffffu, s, o);
    if ((tid & 31) == 0) wred[tid >> 5] = s;
    __syncthreads();
    float x2 = 0.f;
#pragma unroll
    for (int w = 0; w < 8; w++) x2 += wred[w];

    if (tid < P) {
        const float d = x2 + ((red[0][tid] + red[1][tid]) +
                              (red[2][tid] + red[3][tid]));
        dist[tid] = d;
        out[O2 + (size_t)b * P + tid] = d;
    }
    __syncthreads();

    // argmin, first-min tie-break (matches jnp.argmin)
    if (tid < 32) {
        float v0 = dist[tid], v1 = dist[tid + 32];
        float v; int ix;
        if (v1 < v0) { v = v1; ix = tid + 32; } else { v = v0; ix = tid; }
#pragma unroll
        for (int o = 16; o; o >>= 1) {
            const float ov = __shfl_down_sync(0xffffffffu, v, o);
            const int   oi = __shfl_down_sync(0xffffffffu, ix, o);
            if (ov < v || (ov == v && oi < ix)) { v = ov; ix = oi; }
        }
        if (tid == 0) {
            sidx = ix;
            out[O3 + b] = (float)ix;
            out[O4 + b] = (float)label[b];
        }
    }
    __syncthreads();

    // gather selected prototype
    const float2* pr = (const float2*)(proto + (size_t)sidx * K);
    float2* o0 = (float2*)(out + (size_t)b * K);
    for (int i = tid; i < K / 2; i += 256) o0[i] = pr[i];
}

// ---------------------------------------------------------------------------
extern "C" void kernel_launch(void* const* d_in, const int* in_sizes, int n_in,
                              void* d_out, int out_size) {
    (void)in_sizes; (void)n_in; (void)out_size;
    const float* x     = (const float*)d_in[0];
    const float* mask  = (const float*)d_in[1];
    const int*   label = (const int*)  d_in[2];
    const float* proto = (const float*)d_in[3];
    float* out = (float*)d_out;

    gemm_kernel<<<dim3(8, NKC), 128>>>(x, mask, proto);
    epi_kernel<<<B + NCPY, 256>>>(x, mask, label, proto, out);
}

// round 15
// speedup vs baseline: 1.3892x; 1.1301x over previous
#include <cuda_runtime.h>

// Problem constants
constexpr int B = 512, T = 365, C = 10, P = 64;
constexpr int K  = T * C;       // 3650
constexpr int KE = K + T;       // 4015
constexpr int KC  = 64;         // k per CTA chunk (4 stages of 16)
constexpr int NKC = 63;         // chunks cover [0, 4032) ⊇ KE
constexpr int NB_GEMM = 8 * NKC;   // 504 gemm CTAs
constexpr int NB_COPY = 128;       // copy CTAs

// Output layout: [output_seq BK][input_seq BK][distances BP][indices B][label B][mask BT]
constexpr int O1 = B * K;
constexpr int O2 = O1 + B * K;
constexpr int O3 = O2 + B * P;
constexpr int O4 = O3 + B;
constexpr int O5 = O4 + B;

__device__ float g_part[NKC * B * P];   // split-K partials (~8.3 MB, L2)
__device__ float g_x2p[NKC * B];        // per-chunk x2 partials (129 KB)

// ---------------------------------------------------------------------------
// Mega kernel. Blocks [0,504): fused split-K SGEMM (+x2 partials).
// Blocks [504,632): grid-stride copies of input_seq and mask (overlapped BW).
// GEMM: A[b,kk] = kk<K ? x*mask : (kk<KE ? mask[b,kk-K] : 0)
//       Bm[p,kk] = kk<K ? -2*proto : (kk<KE ? q[p,kk-K] : 0)   (on the fly)
// 64x64 C tile, 4x8 per thread, 4-stage (16-k) rolling pipeline, 2 smem bufs.
// smem [k][col], swizzle col' = col ^ ((k>>2)<<3): STS conflict-free,
// LDS.128 one wavefront each.
// ---------------------------------------------------------------------------
__global__ __launch_bounds__(128) void mega_kernel(const float* __restrict__ x,
                                                   const float* __restrict__ mask,
                                                   const float* __restrict__ proto,
                                                   float* __restrict__ out) {
    const int tid = threadIdx.x;

    if (blockIdx.x >= NB_GEMM) {
        // ---- copy lane (float4 grid-stride)
        const int g   = (blockIdx.x - NB_GEMM) * 128 + tid;
        const int gsz = NB_COPY * 128;
        const float4* x4 = (const float4*)x;
        float4* o1 = (float4*)(out + O1);
        for (int i = g; i < B * K / 4; i += gsz) o1[i] = x4[i];
        const float4* m4 = (const float4*)mask;
        float4* o5 = (float4*)(out + O5);
        for (int i = g; i < B * T / 4; i += gsz) o5[i] = m4[i];
        return;
    }

    __shared__ float smA[2 * 16 * 64];
    __shared__ float smB[2 * 16 * 64];
    __shared__ float mT[64 * 8];

    const int btile = blockIdx.x & 7;
    const int kcid  = blockIdx.x >> 3;
    const int b0    = btile * 64;
    const int kbase = kcid * KC;
    const int t0    = kbase / C;

    // mask tile: 8 t-slots cover this 64-k chunk's x-region
    for (int i = tid; i < 64 * 8; i += 128) {
        const int r = i >> 3, tt = i & 7, t = t0 + tt;
        mT[i] = (t < T) ? mask[(b0 + r) * T + t] : 0.f;
    }
    __syncthreads();

    const int k4 = tid & 3;     // float4 k-slot within 16-k stage
    const int rr = tid >> 2;    // 0..31 (rows rr, rr+32)

    float4 va[2], vb[2];
    float x2a[2] = {0.f, 0.f};  // per-thread x2 partial (rows rr, rr+32)

    auto loadA = [&](int s) {
        const int kk0 = kbase + s * 16 + k4 * 4;
        if (kk0 + 3 < K) {
            const int tA = kk0 / C - t0, tB = (kk0 + 1) / C - t0;
            const int tC2 = (kk0 + 2) / C - t0, tD = (kk0 + 3) / C - t0;
#pragma unroll
            for (int i = 0; i < 2; i++) {
                const int r = rr + 32 * i;
                const float* xp = x + (size_t)(b0 + r) * K + kk0;
                const float2 u = *(const float2*)xp;
                const float2 v = *(const float2*)(xp + 2);
                const float* m = mT + r * 8;
                va[i] = make_float4(u.x * m[tA], u.y * m[tB],
                                    v.x * m[tC2], v.y * m[tD]);
                x2a[i] = fmaf(va[i].x, va[i].x, x2a[i]);
                x2a[i] = fmaf(va[i].y, va[i].y, x2a[i]);
                x2a[i] = fmaf(va[i].z, va[i].z, x2a[i]);
                x2a[i] = fmaf(va[i].w, va[i].w, x2a[i]);
            }
        } else {
#pragma unroll
            for (int i = 0; i < 2; i++) {
                const int r = rr + 32 * i;
                float w[4];
#pragma unroll
                for (int j = 0; j < 4; j++) {
                    const int kk = kk0 + j;
                    float v = 0.f;
                    if (kk < K) {
                        v = x[(size_t)(b0 + r) * K + kk] * mT[r * 8 + (kk / C - t0)];
                        x2a[i] = fmaf(v, v, x2a[i]);
                    } else if (kk < KE) {
                        v = mask[(b0 + r) * T + (kk - K)];
                    }
                    w[j] = v;
                }
                va[i] = make_float4(w[0], w[1], w[2], w[3]);
            }
        }
    };
    auto loadB = [&](int s) {
        const int kk0 = kbase + s * 16 + k4 * 4;
        if (kk0 + 3 < K) {
#pragma unroll
            for (int i = 0; i < 2; i++) {
                const int p = rr + 32 * i;
                const float* pp = proto + (size_t)p * K + kk0;
                const float2 u = *(const float2*)pp;
                const float2 v = *(const float2*)(pp + 2);
                vb[i] = make_float4(-2.f * u.x, -2.f * u.y, -2.f * v.x, -2.f * v.y);
            }
        } else {
#pragma unroll
            for (int i = 0; i < 2; i++) {
                const int p = rr + 32 * i;
                float w[4];
#pragma unroll
                for (int j = 0; j < 4; j++) {
                    const int kk = kk0 + j;
                    float v = 0.f;
                    if (kk < K) {
                        v = -2.f * proto[(size_t)p * K + kk];
                    } else if (kk < KE) {
                        const int t = kk - K;
                        const float* pr = proto + (size_t)p * K + t * C;
                        float s2 = 0.f;
#pragma unroll
                        for (int c = 0; c < C; c += 2) {
                            const float2 q2 = *(const float2*)(pr + c);
                            s2 = fmaf(q2.x, q2.x, fmaf(q2.y, q2.y, s2));
                        }
                        v = s2;
                    }
                    w[j] = v;
                }
                vb[i] = make_float4(w[0], w[1], w[2], w[3]);
            }
        }
    };

    const int cs = k4 << 3;     // store swizzle (float level)
    auto storeA = [&](int s) {
        float* base = smA + (s & 1) * 1024 + (k4 * 4) * 64;
#pragma unroll
        for (int i = 0; i < 2; i++) {
            const int col = (rr + 32 * i) ^ cs;
            base[col]       = va[i].x;
            base[64 + col]  = va[i].y;
            base[128 + col] = va[i].z;
            base[192 + col] = va[i].w;
        }
    };
    auto storeB = [&](int s) {
        float* base = smB + (s & 1) * 1024 + (k4 * 4) * 64;
#pragma unroll
        for (int i = 0; i < 2; i++) {
            const int col = (rr + 32 * i) ^ cs;
            base[col]       = vb[i].x;
            base[64 + col]  = vb[i].y;
            base[128 + col] = vb[i].z;
            base[192 + col] = vb[i].w;
        }
    };

    const int tx = tid & 7;     // p: 8tx..8tx+7
    const int ty = tid >> 3;    // m: 4ty..4ty+3
    float acc[4][8] = {};

    auto compute = [&](int s) {
        const float* As = smA + (s & 1) * 1024;
        const float* Bs = smB + (s & 1) * 1024;
#pragma unroll
        for (int k = 0; k < 16; k++) {
            const int sw = (k >> 2) << 1;           // float4-level swizzle
            const float4 a  = ((const float4*)(As + k * 64))[ty ^ sw];
            const float4 q0 = ((const float4*)(Bs + k * 64))[(2 * tx) ^ sw];
            const float4 q1 = ((const float4*)(Bs + k * 64))[(2 * tx + 1) ^ sw];
            const float av[4] = {a.x, a.y, a.z, a.w};
            const float bv[8] = {q0.x, q0.y, q0.z, q0.w, q1.x, q1.y, q1.z, q1.w};
#pragma unroll
            for (int e = 0; e < 4; e++)
#pragma unroll
                for (int jj = 0; jj < 8; jj++)
                    acc[e][jj] = fmaf(av[e], bv[jj], acc[e][jj]);
        }
    };

    // 4-stage rolling pipeline, 2 smem buffers
    loadA(0); loadB(0);
    storeA(0); storeB(0);
    loadA(1); loadB(1);
    __syncthreads();
#pragma unroll
    for (int s = 0; s < 4; s++) {
        if (s + 1 < 4) { storeA(s + 1); storeB(s + 1); }
        if (s + 2 < 4) { loadA(s + 2); loadB(s + 2); }
        compute(s);
        __syncthreads();
    }

    // x2 partials: reduce across the 4 k-slots sharing each row (lane bits 0-1)
#pragma unroll
    for (int i = 0; i < 2; i++) {
        x2a[i] += __shfl_xor_sync(0xffffffffu, x2a[i], 1);
        x2a[i] += __shfl_xor_sync(0xffffffffu, x2a[i], 2);
    }
    if (k4 == 0) {
        g_x2p[kcid * B + b0 + rr]      = x2a[0];
        g_x2p[kcid * B + b0 + rr + 32] = x2a[1];
    }

    // partial stores (rows 4ty..+3, cols 8tx..+7)
    float* dst = g_part + ((size_t)kcid * B + b0 + ty * 4) * P + tx * 8;
#pragma unroll
    for (int e = 0; e < 4; e++) {
        *(float4*)(dst + (size_t)e * P)     = make_float4(acc[e][0], acc[e][1],
                                                          acc[e][2], acc[e][3]);
        *(float4*)(dst + (size_t)e * P + 4) = make_float4(acc[e][4], acc[e][5],
                                                          acc[e][6], acc[e][7]);
    }
}

// ---------------------------------------------------------------------------
// Dist kernel: one CTA per b (256 threads). No x/mask reads.
// Reduce partials + x2 partials, distances, argmin, label, gather.
// ---------------------------------------------------------------------------
__global__ __launch_bounds__(256) void dist_kernel(const int* __restrict__ label,
                                                   const float* __restrict__ proto,
                                                   float* __restrict__ out) {
    __shared__ float red[4][P];
    __shared__ float dist[P];
    __shared__ float sx2;
    __shared__ int sidx;

    const int b = blockIdx.x, tid = threadIdx.x;

    // split-K reduce: p = tid&63, stripe h = tid>>6, 4-way MLP accumulators
    {
        const int p = tid & 63, h = tid >> 6;
        const float* src = g_part + (size_t)b * P + p;
        float s0 = 0.f, s1 = 0.f, s2 = 0.f, s3 = 0.f;
        int kc = h;
        for (; kc + 12 < NKC; kc += 16) {
            s0 += src[(size_t)(kc)      * B * P];
            s1 += src[(size_t)(kc + 4)  * B * P];
            s2 += src[(size_t)(kc + 8)  * B * P];
            s3 += src[(size_t)(kc + 12) * B * P];
        }
        for (; kc < NKC; kc += 4) s0 += src[(size_t)kc * B * P];
        red[h][p] = (s0 + s1) + (s2 + s3);
    }

    // x2 reduce (warp 0): 63 partials, 2 per lane
    if (tid < 32) {
        float v = (tid < NKC) ? g_x2p[tid * B + b] : 0.f;
        if (tid + 32 < NKC) v += g_x2p[(tid + 32) * B + b];
#pragma unroll
        for (int o = 16; o; o >>= 1) v += __shfl_down_sync(0xffffffffu, v, o);
        if (tid == 0) sx2 = v;
    }
    __syncthreads();

    if (tid < P) {
        const float d = sx2 + ((red[0][tid] + red[1][tid]) +
                               (red[2][tid] + red[3][tid]));
        dist[tid] = d;
        out[O2 + (size_t)b * P + tid] = d;
    }
    __syncthreads();

    // argmin, first-min tie-break (matches jnp.argmin)
    if (tid < 32) {
        float v0 = dist[tid], v1 = dist[tid + 32];
        float v; int ix;
        if (v1 < v0) { v = v1; ix = tid + 32; } else { v = v0; ix = tid; }
#pragma unroll
        for (int o = 16; o; o >>= 1) {
            const float ov = __shfl_down_sync(0xffffffffu, v, o);
            const int   oi = __shfl_down_sync(0xffffffffu, ix, o);
            if (ov < v || (ov == v && oi < ix)) { v = ov; ix = oi; }
        }
        if (tid == 0) {
            sidx = ix;
            out[O3 + b] = (float)ix;
            out[O4 + b] = (float)label[b];
        }
    }
    __syncthreads();

    // gather selected prototype
    const float2* pr = (const float2*)(proto + (size_t)sidx * K);
    float2* o0 = (float2*)(out + (size_t)b * K);
    for (int i = tid; i < K / 2; i += 256) o0[i] = pr[i];
}

// ---------------------------------------------------------------------------
extern "C" void kernel_launch(void* const* d_in, const int* in_sizes, int n_in,
                              void* d_out, int out_size) {
    (void)in_sizes; (void)n_in; (void)out_size;
    const float* x     = (const float*)d_in[0];
    const float* mask  = (const float*)d_in[1];
    const int*   label = (const int*)  d_in[2];
    const float* proto = (const float*)d_in[3];
    float* out = (float*)d_out;

    mega_kernel<<<NB_GEMM + NB_COPY, 128>>>(x, mask, proto, out);
    dist_kernel<<<B, 256>>>(label, proto, out);
}